// round 1
// baseline (speedup 1.0000x reference)
#include <cuda_runtime.h>
#include <cstdint>

// ---------------------------------------------------------------------------
// CrossWarpingModule: B=2, C=64, H=W=256 -> 4 parity sub-images of 128x128,
// 8-head axial attention (per-head channel dim = 1), flow, bilinear warp.
//
// Pipeline:
//   K1  k_qkv       : 1x1 convs -> Q, K2(=K*log2e), V   [8 sub][8 head][128*128]
//   K1T k_transpose : Q,K2,V -> transposed copies (for vertical axial pass)
//   K2  k_attn      : axial softmax-attention -> flow fields (both directions)
//   K3  k_warp      : bilinear border grid-sample + parity re-interleave
// ---------------------------------------------------------------------------

#define PLANE 16384  // 128*128

__device__ float g_Q  [8][8][PLANE];
__device__ float g_K2 [8][8][PLANE];
__device__ float g_V  [8][8][PLANE];
__device__ float g_QT [8][8][PLANE];
__device__ float g_K2T[8][8][PLANE];
__device__ float g_VT [8][8][PLANE];
// dir 0 = horizontal (line=row h, pos=col w), dir 1 = vertical (line=col w, pos=row h)
__device__ float g_flow[2][8][PLANE];

// ---------------------------------------------------------------------------
// K1: QKV projections. One thread handles 4 consecutive original-x pixels
// (float4 loads), scattering results into the 4 parity sub-image planes.
// ---------------------------------------------------------------------------
__global__ __launch_bounds__(256) void k_qkv(
    const float* __restrict__ cur, const float* __restrict__ ref,
    const float* __restrict__ Wq, const float* __restrict__ Wk,
    const float* __restrict__ Wv)
{
    __shared__ float sW[3][512];
    int t = threadIdx.x;
    for (int i = t; i < 512; i += 256) {
        sW[0][i] = Wq[i];
        sW[1][i] = Wk[i] * 1.4426950408889634f;  // fold log2(e) into K
        sW[2][i] = Wv[i];
    }
    __syncthreads();

    int idx = blockIdx.x * 256 + t;      // 32768 total = 2(b) * 256(y) * 64(xq)
    int b   = idx >> 14;
    int rem = idx & 16383;
    int y   = rem >> 6;
    int xq  = rem & 63;
    int h2  = y >> 1, dyp = y & 1;

    float4 qa[8], ka[8], va[8];
#pragma unroll
    for (int h = 0; h < 8; ++h) {
        qa[h] = make_float4(0.f, 0.f, 0.f, 0.f);
        ka[h] = make_float4(0.f, 0.f, 0.f, 0.f);
        va[h] = make_float4(0.f, 0.f, 0.f, 0.f);
    }

    const float* curp = cur + ((size_t)b * 64) * 65536 + y * 256 + xq * 4;
    const float* refp = ref + ((size_t)b * 64) * 65536 + y * 256 + xq * 4;

#pragma unroll 2
    for (int c = 0; c < 64; ++c) {
        float4 cv = *(const float4*)(curp + (size_t)c * 65536);
        float4 rv = *(const float4*)(refp + (size_t)c * 65536);
#pragma unroll
        for (int h = 0; h < 8; ++h) {
            float wq = sW[0][h * 64 + c];
            float wk = sW[1][h * 64 + c];
            float wv = sW[2][h * 64 + c];
            qa[h].x = fmaf(wq, cv.x, qa[h].x);
            qa[h].y = fmaf(wq, cv.y, qa[h].y);
            qa[h].z = fmaf(wq, cv.z, qa[h].z);
            qa[h].w = fmaf(wq, cv.w, qa[h].w);
            ka[h].x = fmaf(wk, rv.x, ka[h].x);
            ka[h].y = fmaf(wk, rv.y, ka[h].y);
            ka[h].z = fmaf(wk, rv.z, ka[h].z);
            ka[h].w = fmaf(wk, rv.w, ka[h].w);
            va[h].x = fmaf(wv, rv.x, va[h].x);
            va[h].y = fmaf(wv, rv.y, va[h].y);
            va[h].z = fmaf(wv, rv.z, va[h].z);
            va[h].w = fmaf(wv, rv.w, va[h].w);
        }
    }

    // parity sub mapping: (dy,dx) -> s : (0,0)->0 (1,1)->1 (0,1)->2 (1,0)->3
    int s0  = dyp ? 3 : 0;               // dx = 0 pixels (x components .x, .z)
    int s1  = dyp ? 1 : 2;               // dx = 1 pixels (.y, .w)
    int sb0 = s0 * 2 + b, sb1 = s1 * 2 + b;
    int off = h2 * 128 + xq * 2;
#pragma unroll
    for (int h = 0; h < 8; ++h) {
        *(float2*)&g_Q [sb0][h][off] = make_float2(qa[h].x, qa[h].z);
        *(float2*)&g_Q [sb1][h][off] = make_float2(qa[h].y, qa[h].w);
        *(float2*)&g_K2[sb0][h][off] = make_float2(ka[h].x, ka[h].z);
        *(float2*)&g_K2[sb1][h][off] = make_float2(ka[h].y, ka[h].w);
        *(float2*)&g_V [sb0][h][off] = make_float2(va[h].x, va[h].z);
        *(float2*)&g_V [sb1][h][off] = make_float2(va[h].y, va[h].w);
    }
}

// ---------------------------------------------------------------------------
// K1T: tiled 128x128 plane transpose for Q, K2, V (64 planes each).
// ---------------------------------------------------------------------------
__global__ __launch_bounds__(256) void k_transpose()
{
    __shared__ float tile[32][33];
    int plane = blockIdx.y;              // 0..63
    const float* src;
    float* dst;
    if (blockIdx.z == 0)      { src = &g_Q [0][0][0]; dst = &g_QT [0][0][0]; }
    else if (blockIdx.z == 1) { src = &g_K2[0][0][0]; dst = &g_K2T[0][0][0]; }
    else                      { src = &g_V [0][0][0]; dst = &g_VT [0][0][0]; }
    src += (size_t)plane * PLANE;
    dst += (size_t)plane * PLANE;

    int tx = threadIdx.x, ty = threadIdx.y;           // 32 x 8
    int tilex = (blockIdx.x & 3) * 32;
    int tiley = (blockIdx.x >> 2) * 32;
#pragma unroll
    for (int k = 0; k < 4; ++k)
        tile[ty + k * 8][tx] = src[(tiley + ty + k * 8) * 128 + tilex + tx];
    __syncthreads();
#pragma unroll
    for (int k = 0; k < 4; ++k)
        dst[(tilex + ty + k * 8) * 128 + tiley + tx] = tile[tx][ty + k * 8];
}

// ---------------------------------------------------------------------------
// K2: axial attention. Block = (dir, sub, 2 lines). 256 threads, each thread
// owns one (line,pos) and loops 8 heads; inner loop over 128 keys with an
// FFMA-only exp (magic-round + degree-4 2^r polynomial). Scores are O(1), so
// no max-subtraction is needed for fp32 stability.
// ---------------------------------------------------------------------------
#define EXP_MAGIC 12582912.0f  // 1.5 * 2^23

#define ESTEP(KV, VV)                                          \
    {                                                          \
        float z  = fmaf(q, (KV), EXP_MAGIC);                   \
        int   nb = __float_as_int(z) << 23;                    \
        float r  = fmaf(q, (KV), EXP_MAGIC - z);               \
        float p  = fmaf(r, 0.0096181292f, 0.0555041087f);      \
        p = fmaf(p, r, 0.2402265070f);                         \
        p = fmaf(p, r, 0.6931471806f);                         \
        p = fmaf(p, r, 1.0f);                                  \
        float e = __int_as_float(__float_as_int(p) + nb);      \
        den += e;                                              \
        num = fmaf(e, (VV), num);                              \
    }

__global__ __launch_bounds__(256) void k_attn(
    const float* __restrict__ Wver, const float* __restrict__ Whor)
{
    __shared__ __align__(16) float s[3][8][256];
    __shared__ float swd[8];

    int t   = threadIdx.x;
    int bid = blockIdx.x;                 // 1024 = 2 dir * 8 sub * 64 groups
    int dir = bid >> 9;
    int sb  = (bid >> 6) & 7;
    int grp = bid & 63;
    int base = grp * 256;                 // line0*128, two lines contiguous

    const float* qp = dir ? &g_QT [sb][0][0] : &g_Q [sb][0][0];
    const float* kp = dir ? &g_K2T[sb][0][0] : &g_K2[sb][0][0];
    const float* vp = dir ? &g_VT [sb][0][0] : &g_V [sb][0][0];

    for (int i = t; i < 2048; i += 256) {
        int head = i >> 8, off = i & 255;
        s[0][head][off] = qp[head * PLANE + base + off];
        s[1][head][off] = kp[head * PLANE + base + off];
        s[2][head][off] = vp[head * PLANE + base + off];
    }
    if (t < 8) swd[t] = dir ? Wver[t] : Whor[t];
    __syncthreads();

    int pos  = t & 127;
    int lsel = t >> 7;                    // which of the 2 lines
    float facc = 0.f;

    for (int head = 0; head < 8; ++head) {
        float q = s[0][head][(lsel << 7) + pos];
        const float4* kk = (const float4*)&s[1][head][lsel << 7];
        const float4* vv = (const float4*)&s[2][head][lsel << 7];
        float den = 0.f, num = 0.f;
#pragma unroll 4
        for (int j = 0; j < 32; ++j) {
            float4 k4 = kk[j];
            float4 v4 = vv[j];
            ESTEP(k4.x, v4.x)
            ESTEP(k4.y, v4.y)
            ESTEP(k4.z, v4.z)
            ESTEP(k4.w, v4.w)
        }
        facc = fmaf(swd[head], __fdividef(num, den), facc);
    }
    g_flow[dir][sb][base + t] = facc;     // (lsel*128 + pos) == t
}

// ---------------------------------------------------------------------------
// K3: bilinear border grid-sample of ref sub-images + parity re-interleave.
// Sample coords reduce exactly to (w + flow_x, h + flow_y) in sub-image space.
// ---------------------------------------------------------------------------
__global__ __launch_bounds__(256) void k_warp(
    const float* __restrict__ ref, float* __restrict__ out)
{
    int idx = blockIdx.x * 256 + threadIdx.x;   // 131072 sub-pixels
    int sb  = idx >> 14;
    int rem = idx & 16383;
    int h2  = rem >> 7, w2 = rem & 127;
    int s   = sb >> 1, b = sb & 1;
    int dy  = (s == 1 || s == 3) ? 1 : 0;       // {0,1,0,1}[s]
    int dx  = (s == 1 || s == 2) ? 1 : 0;       // {0,1,1,0}[s]

    float fx = g_flow[0][sb][(h2 << 7) + w2];
    float fy = g_flow[1][sb][(w2 << 7) + h2];
    float ix = (float)w2 + fx;
    float iy = (float)h2 + fy;
    float x0f = floorf(ix), y0f = floorf(iy);
    float wx = ix - x0f, wy = iy - y0f;
    int x0 = (int)x0f, y0 = (int)y0f;
    int x0c = min(max(x0, 0), 127), x1c = min(max(x0 + 1, 0), 127);
    int y0c = min(max(y0, 0), 127), y1c = min(max(y0 + 1, 0), 127);

    int X0 = 2 * x0c + dx, X1 = 2 * x1c + dx;
    int Y0 = 2 * y0c + dy, Y1 = 2 * y1c + dy;
    int o00 = Y0 * 256 + X0, o01 = Y0 * 256 + X1;
    int o10 = Y1 * 256 + X0, o11 = Y1 * 256 + X1;

    float w11 = wx * wy;
    float w01 = wx - w11;
    float w10 = wy - w11;
    float w00 = 1.f - wx - wy + w11;

    const float* rp = ref + (size_t)b * 64 * 65536;
    float*       op = out + (size_t)b * 64 * 65536 + (2 * h2 + dy) * 256 + (2 * w2 + dx);

#pragma unroll 4
    for (int c = 0; c < 64; ++c) {
        const float* p = rp + (size_t)c * 65536;
        float v = w00 * p[o00];
        v = fmaf(w01, p[o01], v);
        v = fmaf(w10, p[o10], v);
        v = fmaf(w11, p[o11], v);
        op[(size_t)c * 65536] = v;
    }
}

// ---------------------------------------------------------------------------
extern "C" void kernel_launch(void* const* d_in, const int* in_sizes, int n_in,
                              void* d_out, int out_size)
{
    const float* cur  = (const float*)d_in[0];
    const float* ref  = (const float*)d_in[1];
    const float* Wq   = (const float*)d_in[2];
    const float* Wk   = (const float*)d_in[3];
    const float* Wv   = (const float*)d_in[4];
    const float* Wver = (const float*)d_in[5];
    const float* Whor = (const float*)d_in[6];
    float* out = (float*)d_out;

    k_qkv<<<128, 256>>>(cur, ref, Wq, Wk, Wv);
    k_transpose<<<dim3(16, 64, 3), dim3(32, 8)>>>();
    k_attn<<<1024, 256>>>(Wver, Whor);
    k_warp<<<512, 256>>>(ref, out);
}

// round 2
// speedup vs baseline: 1.1851x; 1.1851x over previous
#include <cuda_runtime.h>
#include <cstdint>

// ---------------------------------------------------------------------------
// CrossWarpingModule: B=2, C=64, H=W=256 -> 4 parity sub-images of 128x128,
// 8-head axial attention (per-head channel dim = 1), flow, bilinear warp.
//
//   K1  k_qkv       : 1x1 convs -> Q, K2(=K*log2e), V
//   K1T k_transpose : transposed copies for the vertical axial pass
//   K2  k_attn      : axial softmax -> flow. Exp split across MUFU.EX2 and a
//                     packed fma.rn.f32x2 (FFMA2) magic-round+deg3 polynomial
//                     so BOTH the MUFU and FMA pipes are saturated.
//   K3  k_warp      : bilinear border grid-sample + parity re-interleave,
//                     channel-split 4x for occupancy.
// ---------------------------------------------------------------------------

#define PLANE 16384  // 128*128
typedef unsigned long long u64;
typedef unsigned int u32;

__device__ float g_Q  [8][8][PLANE];
__device__ float g_K2 [8][8][PLANE];
__device__ float g_V  [8][8][PLANE];
__device__ float g_QT [8][8][PLANE];
__device__ float g_K2T[8][8][PLANE];
__device__ float g_VT [8][8][PLANE];
__device__ float g_flow[2][8][PLANE];   // dir0 = horizontal, dir1 = vertical

// ------------------------- packed f32x2 helpers ----------------------------
__device__ __forceinline__ u64 pk2f(float lo, float hi) {
    u64 r; asm("mov.b64 %0,{%1,%2};" : "=l"(r) : "f"(lo), "f"(hi)); return r;
}
__device__ __forceinline__ void upk2f(u64 v, float& lo, float& hi) {
    asm("mov.b64 {%0,%1},%2;" : "=f"(lo), "=f"(hi) : "l"(v));
}
__device__ __forceinline__ u64 pk2u(u32 lo, u32 hi) {
    u64 r; asm("mov.b64 %0,{%1,%2};" : "=l"(r) : "r"(lo), "r"(hi)); return r;
}
__device__ __forceinline__ void upk2u(u64 v, u32& lo, u32& hi) {
    asm("mov.b64 {%0,%1},%2;" : "=r"(lo), "=r"(hi) : "l"(v));
}
__device__ __forceinline__ u64 fma2(u64 a, u64 b, u64 c) {
    u64 d; asm("fma.rn.f32x2 %0,%1,%2,%3;" : "=l"(d) : "l"(a), "l"(b), "l"(c)); return d;
}
__device__ __forceinline__ u64 add2(u64 a, u64 b) {
    u64 d; asm("add.rn.f32x2 %0,%1,%2;" : "=l"(d) : "l"(a), "l"(b)); return d;
}
__device__ __forceinline__ u64 mul2(u64 a, u64 b) {
    u64 d; asm("mul.rn.f32x2 %0,%1,%2;" : "=l"(d) : "l"(a), "l"(b)); return d;
}
__device__ __forceinline__ float ex2a(float x) {
    float e; asm("ex2.approx.f32 %0,%1;" : "=f"(e) : "f"(x)); return e;
}

// ---------------------------------------------------------------------------
// K1: QKV projections. One thread handles 4 consecutive original-x pixels.
// ---------------------------------------------------------------------------
__global__ __launch_bounds__(256) void k_qkv(
    const float* __restrict__ cur, const float* __restrict__ ref,
    const float* __restrict__ Wq, const float* __restrict__ Wk,
    const float* __restrict__ Wv)
{
    __shared__ float sW[3][512];
    int t = threadIdx.x;
    for (int i = t; i < 512; i += 256) {
        sW[0][i] = Wq[i];
        sW[1][i] = Wk[i] * 1.4426950408889634f;  // fold log2(e) into K
        sW[2][i] = Wv[i];
    }
    __syncthreads();

    int idx = blockIdx.x * 256 + t;
    int b   = idx >> 14;
    int rem = idx & 16383;
    int y   = rem >> 6;
    int xq  = rem & 63;
    int h2  = y >> 1, dyp = y & 1;

    float4 qa[8], ka[8], va[8];
#pragma unroll
    for (int h = 0; h < 8; ++h) {
        qa[h] = make_float4(0.f, 0.f, 0.f, 0.f);
        ka[h] = make_float4(0.f, 0.f, 0.f, 0.f);
        va[h] = make_float4(0.f, 0.f, 0.f, 0.f);
    }

    const float* curp = cur + ((size_t)b * 64) * 65536 + y * 256 + xq * 4;
    const float* refp = ref + ((size_t)b * 64) * 65536 + y * 256 + xq * 4;

#pragma unroll 2
    for (int c = 0; c < 64; ++c) {
        float4 cv = *(const float4*)(curp + (size_t)c * 65536);
        float4 rv = *(const float4*)(refp + (size_t)c * 65536);
#pragma unroll
        for (int h = 0; h < 8; ++h) {
            float wq = sW[0][h * 64 + c];
            float wk = sW[1][h * 64 + c];
            float wv = sW[2][h * 64 + c];
            qa[h].x = fmaf(wq, cv.x, qa[h].x);
            qa[h].y = fmaf(wq, cv.y, qa[h].y);
            qa[h].z = fmaf(wq, cv.z, qa[h].z);
            qa[h].w = fmaf(wq, cv.w, qa[h].w);
            ka[h].x = fmaf(wk, rv.x, ka[h].x);
            ka[h].y = fmaf(wk, rv.y, ka[h].y);
            ka[h].z = fmaf(wk, rv.z, ka[h].z);
            ka[h].w = fmaf(wk, rv.w, ka[h].w);
            va[h].x = fmaf(wv, rv.x, va[h].x);
            va[h].y = fmaf(wv, rv.y, va[h].y);
            va[h].z = fmaf(wv, rv.z, va[h].z);
            va[h].w = fmaf(wv, rv.w, va[h].w);
        }
    }

    int s0  = dyp ? 3 : 0;
    int s1  = dyp ? 1 : 2;
    int sb0 = s0 * 2 + b, sb1 = s1 * 2 + b;
    int off = h2 * 128 + xq * 2;
#pragma unroll
    for (int h = 0; h < 8; ++h) {
        *(float2*)&g_Q [sb0][h][off] = make_float2(qa[h].x, qa[h].z);
        *(float2*)&g_Q [sb1][h][off] = make_float2(qa[h].y, qa[h].w);
        *(float2*)&g_K2[sb0][h][off] = make_float2(ka[h].x, ka[h].z);
        *(float2*)&g_K2[sb1][h][off] = make_float2(ka[h].y, ka[h].w);
        *(float2*)&g_V [sb0][h][off] = make_float2(va[h].x, va[h].z);
        *(float2*)&g_V [sb1][h][off] = make_float2(va[h].y, va[h].w);
    }
}

// ---------------------------------------------------------------------------
// K1T: tiled 128x128 plane transpose for Q, K2, V.
// ---------------------------------------------------------------------------
__global__ __launch_bounds__(256) void k_transpose()
{
    __shared__ float tile[32][33];
    int plane = blockIdx.y;
    const float* src;
    float* dst;
    if (blockIdx.z == 0)      { src = &g_Q [0][0][0]; dst = &g_QT [0][0][0]; }
    else if (blockIdx.z == 1) { src = &g_K2[0][0][0]; dst = &g_K2T[0][0][0]; }
    else                      { src = &g_V [0][0][0]; dst = &g_VT [0][0][0]; }
    src += (size_t)plane * PLANE;
    dst += (size_t)plane * PLANE;

    int tx = threadIdx.x, ty = threadIdx.y;
    int tilex = (blockIdx.x & 3) * 32;
    int tiley = (blockIdx.x >> 2) * 32;
#pragma unroll
    for (int k = 0; k < 4; ++k)
        tile[ty + k * 8][tx] = src[(tiley + ty + k * 8) * 128 + tilex + tx];
    __syncthreads();
#pragma unroll
    for (int k = 0; k < 4; ++k)
        dst[(tilex + ty + k * 8) * 128 + tiley + tx] = tile[tx][ty + k * 8];
}

// ---------------------------------------------------------------------------
// K2: axial attention, dual-pipe exp.
//  MSTEP: 2 keys via MUFU.EX2               (fma-pipe: 3, mufu: 2)
//  FSTEP: 2 keys via FFMA2 magic-round+deg3 (fma-pipe: 8)
//  Per 16 keys: 5 MSTEP + 3 FSTEP pairs -> fma ~2.44/key, mufu ~0.63/key,
//  both pipes ~balanced.
// ---------------------------------------------------------------------------
#define EXP_MAGIC 12582912.0f  // 1.5 * 2^23

#define MSTEP(K2, V2)                                        \
    {                                                        \
        u64 s2 = mul2(q2, (K2));                             \
        float sl, sh; upk2f(s2, sl, sh);                     \
        u64 e2 = pk2f(ex2a(sl), ex2a(sh));                   \
        den_m = add2(den_m, e2);                             \
        num_m = fma2(e2, (V2), num_m);                       \
    }

#define FSTEP(K2, V2)                                        \
    {                                                        \
        u64 z2 = fma2(q2, (K2), MAGIC2);                     \
        u64 mc2 = fma2(z2, NEG1_2, MAGIC2);                  \
        u64 r2 = fma2(q2, (K2), mc2);                        \
        u64 p2 = fma2(C3_2, r2, C2_2);                       \
        p2 = fma2(p2, r2, C1_2);                             \
        p2 = fma2(p2, r2, C0_2);                             \
        u32 zl, zh, pl, ph;                                  \
        upk2u(z2, zl, zh);                                   \
        upk2u(p2, pl, ph);                                   \
        u64 e2 = pk2u(pl + (zl << 23), ph + (zh << 23));     \
        den_f = add2(den_f, e2);                             \
        num_f = fma2(e2, (V2), num_f);                       \
    }

__global__ __launch_bounds__(256) void k_attn(
    const float* __restrict__ Wver, const float* __restrict__ Whor)
{
    __shared__ __align__(16) float s[3][8][256];
    __shared__ float swd[8];

    int t   = threadIdx.x;
    int bid = blockIdx.x;                 // 1024 = 2 dir * 8 sub * 64 groups
    int dir = bid >> 9;
    int sb  = (bid >> 6) & 7;
    int grp = bid & 63;
    int base = grp * 256;

    const float* qp = dir ? &g_QT [sb][0][0] : &g_Q [sb][0][0];
    const float* kp = dir ? &g_K2T[sb][0][0] : &g_K2[sb][0][0];
    const float* vp = dir ? &g_VT [sb][0][0] : &g_V [sb][0][0];

    for (int i = t; i < 2048; i += 256) {
        int head = i >> 8, off = i & 255;
        s[0][head][off] = qp[head * PLANE + base + off];
        s[1][head][off] = kp[head * PLANE + base + off];
        s[2][head][off] = vp[head * PLANE + base + off];
    }
    if (t < 8) swd[t] = dir ? Wver[t] : Whor[t];
    __syncthreads();

    const u64 MAGIC2 = pk2f(EXP_MAGIC, EXP_MAGIC);
    const u64 NEG1_2 = pk2f(-1.0f, -1.0f);
    // deg-3 Chebyshev fit of 2^r on [-0.5, 0.5], rel err ~1e-4
    const u64 C3_2 = pk2f(0.0559328f, 0.0559328f);
    const u64 C2_2 = pk2f(0.2426208f, 0.2426208f);
    const u64 C1_2 = pk2f(0.6931126f, 0.6931126f);
    const u64 C0_2 = pk2f(0.9999244f, 0.9999244f);

    int pos  = t & 127;
    int lsel = t >> 7;
    float facc = 0.f;

#pragma unroll 1
    for (int head = 0; head < 8; ++head) {
        float q = s[0][head][(lsel << 7) + pos];
        u64 q2 = pk2f(q, q);
        const u64* kk = (const u64*)&s[1][head][lsel << 7];  // 64 key-pairs
        const u64* vv = (const u64*)&s[2][head][lsel << 7];
        u64 den_m = 0ull, num_m = 0ull;   // packed (+0,+0)
        u64 den_f = 0ull, num_f = 0ull;
#pragma unroll 2
        for (int m = 0; m < 8; ++m) {     // 8 pairs = 16 keys per iter
            const u64* kq = kk + m * 8;
            const u64* vq = vv + m * 8;
            MSTEP(kq[0], vq[0])
            MSTEP(kq[1], vq[1])
            MSTEP(kq[2], vq[2])
            MSTEP(kq[3], vq[3])
            MSTEP(kq[4], vq[4])
            FSTEP(kq[5], vq[5])
            FSTEP(kq[6], vq[6])
            FSTEP(kq[7], vq[7])
        }
        u64 den2 = add2(den_m, den_f);
        u64 num2 = add2(num_m, num_f);
        float dl, dh, nl, nh;
        upk2f(den2, dl, dh);
        upk2f(num2, nl, nh);
        facc = fmaf(swd[head], __fdividef(nl + nh, dl + dh), facc);
    }
    g_flow[dir][sb][base + t] = facc;
}

// ---------------------------------------------------------------------------
// K3: bilinear border grid-sample + parity re-interleave.
// 4x channel-split: each thread handles 16 of the 64 channels.
// ---------------------------------------------------------------------------
__global__ __launch_bounds__(256) void k_warp(
    const float* __restrict__ ref, float* __restrict__ out)
{
    int idx = blockIdx.x * 256 + threadIdx.x;   // 524288
    int pix = idx & 16383;
    int cid = (idx >> 14) & 3;                  // channel chunk 0..3
    int sb  = idx >> 16;                        // 0..7
    int h2  = pix >> 7, w2 = pix & 127;
    int s   = sb >> 1, b = sb & 1;
    int dy  = (s == 1 || s == 3) ? 1 : 0;
    int dx  = (s == 1 || s == 2) ? 1 : 0;

    float fx = g_flow[0][sb][(h2 << 7) + w2];
    float fy = g_flow[1][sb][(w2 << 7) + h2];
    float ix = (float)w2 + fx;
    float iy = (float)h2 + fy;
    float x0f = floorf(ix), y0f = floorf(iy);
    float wx = ix - x0f, wy = iy - y0f;
    int x0 = (int)x0f, y0 = (int)y0f;
    int x0c = min(max(x0, 0), 127), x1c = min(max(x0 + 1, 0), 127);
    int y0c = min(max(y0, 0), 127), y1c = min(max(y0 + 1, 0), 127);

    int X0 = 2 * x0c + dx, X1 = 2 * x1c + dx;
    int Y0 = 2 * y0c + dy, Y1 = 2 * y1c + dy;
    int o00 = Y0 * 256 + X0, o01 = Y0 * 256 + X1;
    int o10 = Y1 * 256 + X0, o11 = Y1 * 256 + X1;

    float w11 = wx * wy;
    float w01 = wx - w11;
    float w10 = wy - w11;
    float w00 = 1.f - wx - wy + w11;

    int c0 = cid * 16;
    const float* rp = ref + ((size_t)b * 64 + c0) * 65536;
    float*       op = out + ((size_t)b * 64 + c0) * 65536
                          + (2 * h2 + dy) * 256 + (2 * w2 + dx);

#pragma unroll 4
    for (int c = 0; c < 16; ++c) {
        const float* p = rp + (size_t)c * 65536;
        float v = w00 * p[o00];
        v = fmaf(w01, p[o01], v);
        v = fmaf(w10, p[o10], v);
        v = fmaf(w11, p[o11], v);
        op[(size_t)c * 65536] = v;
    }
}

// ---------------------------------------------------------------------------
extern "C" void kernel_launch(void* const* d_in, const int* in_sizes, int n_in,
                              void* d_out, int out_size)
{
    const float* cur  = (const float*)d_in[0];
    const float* ref  = (const float*)d_in[1];
    const float* Wq   = (const float*)d_in[2];
    const float* Wk   = (const float*)d_in[3];
    const float* Wv   = (const float*)d_in[4];
    const float* Wver = (const float*)d_in[5];
    const float* Whor = (const float*)d_in[6];
    float* out = (float*)d_out;

    k_qkv<<<128, 256>>>(cur, ref, Wq, Wk, Wv);
    k_transpose<<<dim3(16, 64, 3), dim3(32, 8)>>>();
    k_attn<<<1024, 256>>>(Wver, Whor);
    k_warp<<<2048, 256>>>(ref, out);
}